// round 15
// baseline (speedup 1.0000x reference)
#include <cuda_runtime.h>
#include <cuda_bf16.h>
#include <math.h>

// Problem constants
#define BDIM   8
#define TDIM   2048
#define DDIM   1024
#define EDIM   4
#define KCB    64
#define NTAGS  512
#define G3D    3072   // 3*DDIM
#define MAXSPAN 128

#define SCREEN_MARGIN 4.0f

// -------- scratch (device globals; no allocation allowed) --------
__device__ float g_X   [NTAGS * DDIM];
__device__ float g_GihA[NTAGS * G3D];         // split-K half 0 (compact GRU rows)
__device__ float g_GihB[NTAGS * G3D];         // split-K half 1
__device__ float g_Ghh [(KCB + 1) * G3D];
__device__ float g_cb  [(KCB + 1) * DDIM];
__device__ __nv_bfloat162 g_cbH[KCB * 512];
__device__ float g_injT[KCB * DDIM];
__device__ float g_cnorm[KCB];
// schedule / span state
__device__ short g_st  [BDIM][NTAGS];
__device__ short g_sp2 [BDIM][NTAGS];
__device__ int   g_nact [BDIM];
__device__ int   g_nspan[BDIM];
__device__ short g_span_start[BDIM][MAXSPAN];
__device__ short g_span_len  [BDIM][MAXSPAN];
__device__ unsigned char g_code[BDIM][NTAGS];
__device__ float g_commit_span[BDIM * MAXSPAN];
// GRU-row compaction
__device__ short g_gruLocTag[BDIM][NTAGS];    // per-batch compact GRU tag list
__device__ short g_gihLoc[BDIM][NTAGS];       // per active step: local gru index
__device__ int   g_nGruB[BDIM];
__device__ int   g_gruOff[BDIM];
__device__ int   g_nGru;
__device__ short g_gruTag[NTAGS];             // global compact tag list

// ---- packed fp32x2 helpers ----
#define FFMA2(acc, a, bsp) \
    asm("fma.rn.f32x2 %0, %1, %2, %0;" : "+l"(acc) : "l"(a), "l"(bsp))
#define SPLAT2(d, f) \
    asm("mov.b64 %0, {%1, %1};" : "=l"(d) : "r"(__float_as_uint(f)))

// -------- gather h rows for each tag --------
__global__ void gather_x(const float* __restrict__ h,
                         const int* __restrict__ bidx,
                         const int* __restrict__ spos) {
    int t = blockIdx.x;
    int e = threadIdx.x;
    const float4* src = (const float4*)(h + ((size_t)bidx[t] * TDIM + spos[t]) * DDIM);
    float4* dst = (float4*)(g_X + (size_t)t * DDIM);
    dst[e] = src[e];
}

// -------- codebook copy (+zero row), norms, row-major bf16 copy --------
__global__ void prep_cb(const float* __restrict__ cb) {
    int k = blockIdx.x;
    int tid = threadIdx.x;
    float part = 0.f;
    for (int e = tid; e < DDIM; e += 256) {
        float v = (k < KCB) ? cb[(size_t)k * DDIM + e] : 0.f;
        g_cb[(size_t)k * DDIM + e] = v;
        part += v * v;
    }
    if (k < KCB) {
        for (int p = tid; p < 512; p += 256)
            g_cbH[k * 512 + p] = __floats2bfloat162_rn(cb[(size_t)k * DDIM + 2 * p],
                                                       cb[(size_t)k * DDIM + 2 * p + 1]);
    }
    __shared__ float red[256];
    red[tid] = part;
    __syncthreads();
    for (int s = 128; s > 0; s >>= 1) {
        if (tid < s) red[tid] += red[tid + s];
        __syncthreads();
    }
    if (tid == 0 && k < KCB) g_cnorm[k] = red[0];
}

// ============================================================================
// build_sched: per-batch active steps + span table + per-batch GRU compaction.
// ============================================================================
__global__ __launch_bounds__(512)
void build_sched(const int* __restrict__ bidx, const int* __restrict__ spos,
                 const int* __restrict__ tok, const int* __restrict__ ctag) {
    const int b = blockIdx.x;
    const int tid = threadIdx.x;
    __shared__ int s_scan[NTAGS];
    __shared__ int s_nchar, s_nact;

    const int char_tag = ctag ? *ctag : 0;
    const int inb  = (bidx[tid] == b) ? 1 : 0;
    const int isch = (inb && tok[tid] == char_tag) ? 1 : 0;
    s_scan[tid] = isch;
    __syncthreads();
    for (int off = 1; off < NTAGS; off <<= 1) {
        int v = s_scan[tid];
        if (tid >= off) v += s_scan[tid - off];
        __syncthreads();
        s_scan[tid] = v;
        __syncthreads();
    }
    const int chars_before = s_scan[tid] - isch;
    if (tid == NTAGS - 1) s_nchar = s_scan[NTAGS - 1];
    const int active = (inb && (isch || chars_before > 0)) ? 1 : 0;
    __syncthreads();
    s_scan[tid] = active;
    __syncthreads();
    for (int off = 1; off < NTAGS; off <<= 1) {
        int v = s_scan[tid];
        if (tid >= off) v += s_scan[tid - off];
        __syncthreads();
        s_scan[tid] = v;
        __syncthreads();
    }
    if (active) {
        int pos = s_scan[tid] - 1;
        g_st [b][pos] = (short)tid;
        g_sp2[b][pos] = (short)spos[tid];
        if (isch && chars_before < MAXSPAN)
            g_span_start[b][chars_before] = (short)pos;
        if (!isch) {
            int gl = pos - chars_before;       // non-char actives before this one
            g_gihLoc[b][pos] = (short)gl;
            g_gruLocTag[b][gl] = (short)tid;
        }
    }
    if (tid == NTAGS - 1) s_nact = s_scan[NTAGS - 1];
    __syncthreads();

    int nchar = s_nchar; if (nchar > MAXSPAN) nchar = MAXSPAN;
    const int nact = s_nact;
    for (int c = tid; c < MAXSPAN; c += 512) g_commit_span[b * MAXSPAN + c] = 0.f;
    if (tid < nchar) {
        int st = g_span_start[b][tid];
        int en = (tid + 1 < nchar) ? g_span_start[b][tid + 1] : nact;
        g_span_len[b][tid] = (short)(en - st);
    }
    if (tid == 0) {
        g_nspan[b] = nchar;
        g_nact[b] = nact;
        g_nGruB[b] = nact - s_nchar;           // GRU steps = actives minus chars
    }
}

// ---- concat per-batch GRU tag lists into global compact list ----
__global__ __launch_bounds__(512)
void gru_concat() {
    const int b = blockIdx.x;
    const int tid = threadIdx.x;
    int off = 0;
    for (int i = 0; i < b; i++) off += g_nGruB[i];
    const int n = g_nGruB[b];
    for (int i = tid; i < n; i += 512)
        g_gruTag[off + i] = g_gruLocTag[b][i];
    if (tid == 0) {
        g_gruOff[b] = off;
        if (b == 0) {
            int tot = 0;
            for (int i = 0; i < BDIM; i++) tot += g_nGruB[i];
            g_nGru = tot;
        }
    }
}

// ============================================================================
// Fused fp32 GEMM, split-K on mode 0 (Gih):
//   blocks [0,768):   ks=b/384, Gih half -> g_GihA / g_GihB, compact GRU rows
//   blocks [768,864): Ghh  (K=1024)
//   blocks [864,880): injT (K=1024)
// ============================================================================
__global__ __launch_bounds__(128)
void fused_gemm(const float* __restrict__ h,
                const int* __restrict__ bidx, const int* __restrict__ spos,
                const float* __restrict__ W_ih, const float* __restrict__ b_ih,
                const float* __restrict__ W_hh, const float* __restrict__ b_hh,
                const float* __restrict__ W_inj)
{
    __shared__ __align__(16) float As[2][16][68];
    __shared__ __align__(16) float Bs[2][16][68];

    const int b = blockIdx.x;
    const float* Bw;
    const float* bias;
    float* C;
    const float* Abase = nullptr;
    int M, N, bm, bn, mode, klen, koff;
    if (b < 768) {
        const int ks = b / 384;
        const int t = b % 384;
        mode = 0; N = G3D;
        bm = (t / 48) * 64; bn = (t % 48) * 64;
        M = g_nGru;
        if (bm >= M) return;                   // uniform exit, no barriers yet
        klen = 512; koff = ks * 512;
        Bw = W_ih; bias = (ks == 0) ? b_ih : nullptr;
        C = (ks == 0) ? g_GihA : g_GihB;
    } else if (b < 864) {
        int t = b - 768;
        mode = 1; M = KCB + 1; N = G3D;
        bm = (t / 48) * 64; bn = (t % 48) * 64;
        klen = DDIM; koff = 0;
        Bw = W_hh; bias = b_hh; C = g_Ghh; Abase = g_cb;
    } else {
        int t = b - 864;
        mode = 2; M = KCB; N = DDIM;
        bm = 0; bn = t * 64;
        klen = DDIM; koff = 0;
        Bw = W_inj; bias = nullptr; C = g_injT; Abase = g_cb;
    }

    const int tid   = threadIdx.x;
    const int r     = tid >> 1;
    const int halfq = (tid & 1) * 8;

    const float* aRow;
    {
        int gm = bm + r; if (gm > M - 1) gm = M - 1;
        if (mode == 0) {
            int tg = g_gruTag[gm];
            aRow = h + ((size_t)bidx[tg] * TDIM + spos[tg]) * DDIM + koff;
        } else {
            aRow = Abase + (size_t)gm * DDIM;
        }
    }
    const float* bRow = Bw + (size_t)(bn + r) * DDIM + koff;

    const int ty = tid >> 4;
    const int tx = tid & 15;

    unsigned long long acc[4][4];
#pragma unroll
    for (int p = 0; p < 4; p++)
#pragma unroll
        for (int j = 0; j < 4; j++) acc[p][j] = 0ull;

    {
        float4 a0 = *(const float4*)(aRow + halfq);
        float4 a1 = *(const float4*)(aRow + halfq + 4);
        float4 v0 = *(const float4*)(bRow + halfq);
        float4 v1 = *(const float4*)(bRow + halfq + 4);
        As[0][halfq + 0][r] = a0.x; As[0][halfq + 1][r] = a0.y;
        As[0][halfq + 2][r] = a0.z; As[0][halfq + 3][r] = a0.w;
        As[0][halfq + 4][r] = a1.x; As[0][halfq + 5][r] = a1.y;
        As[0][halfq + 6][r] = a1.z; As[0][halfq + 7][r] = a1.w;
        Bs[0][halfq + 0][r] = v0.x; Bs[0][halfq + 1][r] = v0.y;
        Bs[0][halfq + 2][r] = v0.z; Bs[0][halfq + 3][r] = v0.w;
        Bs[0][halfq + 4][r] = v1.x; Bs[0][halfq + 5][r] = v1.y;
        Bs[0][halfq + 6][r] = v1.z; Bs[0][halfq + 7][r] = v1.w;
    }
    __syncthreads();

    int buf = 0;
#pragma unroll 1
    for (int k0 = 0; k0 < klen; k0 += 16) {
        float4 na0, na1, nb0, nb1;
        const bool more = (k0 + 16) < klen;
        if (more) {
            const float* ap = aRow + k0 + 16 + halfq;
            na0 = *(const float4*)(ap);
            na1 = *(const float4*)(ap + 4);
            const float* bp = bRow + k0 + 16 + halfq;
            nb0 = *(const float4*)(bp);
            nb1 = *(const float4*)(bp + 4);
        }

#pragma unroll
        for (int kk = 0; kk < 16; kk++) {
            ulonglong2 aA = *(const ulonglong2*)&As[buf][kk][ty * 8];
            ulonglong2 aB = *(const ulonglong2*)&As[buf][kk][ty * 8 + 4];
            float4 bv = *(const float4*)&Bs[buf][kk][tx * 4];
            unsigned long long s0, s1, s2, s3;
            SPLAT2(s0, bv.x); SPLAT2(s1, bv.y);
            SPLAT2(s2, bv.z); SPLAT2(s3, bv.w);
            FFMA2(acc[0][0], aA.x, s0); FFMA2(acc[0][1], aA.x, s1);
            FFMA2(acc[0][2], aA.x, s2); FFMA2(acc[0][3], aA.x, s3);
            FFMA2(acc[1][0], aA.y, s0); FFMA2(acc[1][1], aA.y, s1);
            FFMA2(acc[1][2], aA.y, s2); FFMA2(acc[1][3], aA.y, s3);
            FFMA2(acc[2][0], aB.x, s0); FFMA2(acc[2][1], aB.x, s1);
            FFMA2(acc[2][2], aB.x, s2); FFMA2(acc[2][3], aB.x, s3);
            FFMA2(acc[3][0], aB.y, s0); FFMA2(acc[3][1], aB.y, s1);
            FFMA2(acc[3][2], aB.y, s2); FFMA2(acc[3][3], aB.y, s3);
        }

        if (more) {
            int nb = buf ^ 1;
            As[nb][halfq + 0][r] = na0.x; As[nb][halfq + 1][r] = na0.y;
            As[nb][halfq + 2][r] = na0.z; As[nb][halfq + 3][r] = na0.w;
            As[nb][halfq + 4][r] = na1.x; As[nb][halfq + 5][r] = na1.y;
            As[nb][halfq + 6][r] = na1.z; As[nb][halfq + 7][r] = na1.w;
            Bs[nb][halfq + 0][r] = nb0.x; Bs[nb][halfq + 1][r] = nb0.y;
            Bs[nb][halfq + 2][r] = nb0.z; Bs[nb][halfq + 3][r] = nb0.w;
            Bs[nb][halfq + 4][r] = nb1.x; Bs[nb][halfq + 5][r] = nb1.y;
            Bs[nb][halfq + 6][r] = nb1.z; Bs[nb][halfq + 7][r] = nb1.w;
        }
        __syncthreads();
        buf ^= 1;
    }

#pragma unroll
    for (int p = 0; p < 4; p++) {
        int gm0 = bm + ty * 8 + 2 * p;
#pragma unroll
        for (int j = 0; j < 4; j++) {
            int gn = bn + tx * 4 + j;
            float add = bias ? bias[gn] : 0.f;
            unsigned long long a = acc[p][j];
            float lo = __uint_as_float((unsigned)(a & 0xffffffffull)) + add;
            float hi = __uint_as_float((unsigned)(a >> 32)) + add;
            if (gm0 < M)     C[(size_t)gm0 * N + gn]       = lo;
            if (gm0 + 1 < M) C[(size_t)(gm0 + 1) * N + gn] = hi;
        }
    }
}

// ---- fast gates (MUFU) ----
__device__ __forceinline__ float fast_sigmoid(float x) {
    float e = __expf(-x);
    return __fdividef(1.f, 1.f + e);
}
__device__ __forceinline__ float fast_tanh(float x) {
    float e = __expf(-2.f * x);
    return __fdividef(1.f - e, 1.f + e);
}

// ============================================================================
// span_scan: one CTA per span. Gih read as A+B (split-K sum) via compact index.
// ============================================================================
__global__ __launch_bounds__(1024)
void span_scan() {
    const int b = blockIdx.x / MAXSPAN;
    const int k = blockIdx.x % MAXSPAN;
    if (k >= g_nspan[b]) return;

    extern __shared__ __align__(16) __nv_bfloat162 s_cbh[];
    const int tid = threadIdx.x;
    const int lane = tid & 31;
    const int w = tid >> 5;

    __shared__ __align__(16) float zbuf[DDIM];
    __shared__ __align__(16) __nv_bfloat162 zbh[DDIM / 2];
    __shared__ float s_sd[64];
    __shared__ float s_cn[64];
    __shared__ float s_d[64];

    if (tid < 64) s_cn[tid] = g_cnorm[tid];
    for (int idx = tid; idx < KCB * 512; idx += 1024)
        s_cbh[idx] = g_cbH[idx];
    __syncthreads();

    const int start = g_span_start[b][k];
    const int len   = g_span_len[b][k];
    const int goff  = g_gruOff[b];

    float commit_acc = 0.f;
    int cur = 0;
    int spec_k = -1;
    float pf_gi0 = 0.f, pf_gi1 = 0.f, pf_gi2 = 0.f, pf_x = 0.f;
    float pf_gh0 = 0.f, pf_gh1 = 0.f, pf_gh2 = 0.f, pf_cur = 0.f;
    {
        int t0 = g_st[b][start];
        pf_x = g_X[(size_t)t0 * DDIM + tid];   // step 0 is always the char
    }

    for (int j = 0; j < len; j++) {
        // ---- phase A: z ----
        float zv;
        if (j == 0) {
            zv = pf_x;
        } else {
            float gh0, gh1, gh2, curv;
            if (cur == spec_k) {
                gh0 = pf_gh0; gh1 = pf_gh1; gh2 = pf_gh2; curv = pf_cur;
            } else {
                const float* gh = g_Ghh + (size_t)cur * G3D;
                gh0 = gh[tid]; gh1 = gh[1024 + tid]; gh2 = gh[2048 + tid];
                curv = g_cb[(size_t)cur * DDIM + tid];
            }
            float rr = fast_sigmoid(pf_gi0 + gh0);
            float zg = fast_sigmoid(pf_gi1 + gh1);
            float nn = fast_tanh(pf_gi2 + rr * gh2);
            zv = (1.f - zg) * nn + zg * curv;
        }
        zbuf[tid] = zv;
        {
            float partner = __shfl_xor_sync(0xffffffffu, zv, 1);
            if ((tid & 1) == 0)
                zbh[tid >> 1] = __floats2bfloat162_rn(zv, partner);
        }
        if (j + 1 < len) {
            int gidx = goff + (int)g_gihLoc[b][start + j + 1];
            const float* giA = g_GihA + (size_t)gidx * G3D;
            const float* giB = g_GihB + (size_t)gidx * G3D;
            pf_gi0 = giA[tid]        + giB[tid];
            pf_gi1 = giA[1024 + tid] + giB[1024 + tid];
            pf_gi2 = giA[2048 + tid] + giB[2048 + tid];
        }
        __syncthreads();                       // sync 1

        // ---- phase B: HFMA2 screen; warp w -> codes 2w, 2w+1 ----
        {
            const int k0 = 2 * w;
            const uint4* zz4 = (const uint4*)zbh;
            const uint4* c0q = (const uint4*)(s_cbh + (size_t)k0 * 512);
            const uint4* c1q = c0q + 128;
            __nv_bfloat162 a00 = __floats2bfloat162_rn(0.f, 0.f);
            __nv_bfloat162 a01 = a00, a10 = a00, a11 = a00;
#pragma unroll
            for (int jq = 0; jq < 4; jq++) {
                uint4 zq = zz4[lane + 32 * jq];
                uint4 cA = c0q[lane + 32 * jq];
                uint4 cB = c1q[lane + 32 * jq];
                const __nv_bfloat162* zp = (const __nv_bfloat162*)&zq;
                const __nv_bfloat162* ap = (const __nv_bfloat162*)&cA;
                const __nv_bfloat162* bp = (const __nv_bfloat162*)&cB;
                a00 = __hfma2(zp[0], ap[0], a00);
                a01 = __hfma2(zp[1], ap[1], a01);
                a00 = __hfma2(zp[2], ap[2], a00);
                a01 = __hfma2(zp[3], ap[3], a01);
                a10 = __hfma2(zp[0], bp[0], a10);
                a11 = __hfma2(zp[1], bp[1], a11);
                a10 = __hfma2(zp[2], bp[2], a10);
                a11 = __hfma2(zp[3], bp[3], a11);
            }
            float2 u0 = __bfloat1622float2(a00);
            float2 u1 = __bfloat1622float2(a01);
            float2 v0 = __bfloat1622float2(a10);
            float2 v1 = __bfloat1622float2(a11);
            float p0 = (u0.x + u0.y) + (u1.x + u1.y);
            float p1 = (v0.x + v0.y) + (v1.x + v1.y);
#pragma unroll
            for (int off = 16; off; off >>= 1) {
                p0 += __shfl_down_sync(0xffffffffu, p0, off);
                p1 += __shfl_down_sync(0xffffffffu, p1, off);
            }
            if (lane == 0) {
                s_sd[k0]     = s_cn[k0]     - 2.f * p0;
                s_sd[k0 + 1] = s_cn[k0 + 1] - 2.f * p1;
            }
        }
        __syncthreads();                       // sync 2

        // ---- phase C: screened argmin (all warps) ----
        float v0c = s_sd[lane];
        float v1c = s_sd[lane + 32];
        float dm = v0c; int im = lane;
        if (v1c < dm) { dm = v1c; im = lane + 32; }
#pragma unroll
        for (int off = 16; off; off >>= 1) {
            float od = __shfl_xor_sync(0xffffffffu, dm, off);
            int   oi = __shfl_xor_sync(0xffffffffu, im, off);
            if (od < dm || (od == dm && oi < im)) { dm = od; im = oi; }
        }
        const int jb = 2 * w;
        const float dj0 = s_sd[jb];
        const float dj1 = s_sd[jb + 1];

        // speculative prefetch of next state row
        {
            const float* gh = g_Ghh + (size_t)im * G3D;
            pf_gh0 = gh[tid]; pf_gh1 = gh[1024 + tid]; pf_gh2 = gh[2048 + tid];
            pf_cur = g_cb[(size_t)im * DDIM + tid];
            spec_k = im;
        }

        // ---- phase D: exact fp32 recheck ----
        {
            const float4* z4 = (const float4*)zbuf;
            const float thr = dm + SCREEN_MARGIN;
#pragma unroll
            for (int jj = 0; jj < 2; jj++) {
                const int jc = jb + jj;
                const float dj = jj ? dj1 : dj0;
                float dx = INFINITY;
                if (dj <= thr) {
                    const float4* cr = (const float4*)(g_cb + (size_t)jc * DDIM);
                    float acc = 0.f;
#pragma unroll
                    for (int q = 0; q < 8; q++) {
                        float4 c = cr[lane + 32 * q];
                        float4 z = z4[lane + 32 * q];
                        float e0 = z.x - c.x, e1 = z.y - c.y;
                        float e2 = z.z - c.z, e3 = z.w - c.w;
                        acc += e0 * e0 + e1 * e1 + e2 * e2 + e3 * e3;
                    }
#pragma unroll
                    for (int off = 16; off; off >>= 1)
                        acc += __shfl_down_sync(0xffffffffu, acc, off);
                    dx = acc;
                }
                if (lane == 0) s_d[jc] = dx;
            }
        }
        __syncthreads();                       // sync 3

        // ---- phase E: exact argmin, state update ----
        {
            float e0 = s_d[lane];
            float e1 = s_d[lane + 32];
            float eb = e0; int ib = lane;
            if (e1 < eb) { eb = e1; ib = lane + 32; }
#pragma unroll
            for (int off = 16; off; off >>= 1) {
                float en = __shfl_xor_sync(0xffffffffu, eb, off);
                int   in_ = __shfl_xor_sync(0xffffffffu, ib, off);
                if (en < eb || (en == eb && in_ < ib)) { eb = en; ib = in_; }
            }
            cur = ib;
            if (tid == 0) {
                g_code[b][start + j] = (unsigned char)ib;
                commit_acc += eb * (1.f / 1024.f);
            }
            if (ib != im) spec_k = -1;
        }
    }

    if (tid == 0) g_commit_span[b * MAXSPAN + k] = commit_acc;
}

// ============================================================================
// flush: per-batch ordered injection writes (last-writer-wins per seq_pos).
// ============================================================================
__global__ __launch_bounds__(1024)
void flush_k(float* __restrict__ out) {
    const int b = blockIdx.x;
    const int tid = threadIdx.x;
    const int lane = tid & 31;
    const int w = tid >> 5;
    __shared__ short s_p2s[NTAGS];
    __shared__ unsigned char s_ck[NTAGS];
    const int nact = g_nact[b];
    for (int i = tid; i < nact; i += 1024) {
        s_p2s[i] = g_sp2[b][i];
        s_ck[i]  = g_code[b][i];
    }
    __syncthreads();
    for (int i = w; i < nact; i += 32) {
        const int p = s_p2s[i];
        bool dup = false;
        for (int j = i + 1 + lane; j < nact; j += 32)
            dup |= (s_p2s[j] == p);
        dup = __any_sync(0xffffffffu, dup);
        if (!dup) {
            const int k = s_ck[i];
            const float4* src = (const float4*)(g_injT + (size_t)k * DDIM);
            float4* dst = (float4*)(out + ((size_t)b * TDIM + p) * DDIM);
#pragma unroll
            for (int e = 0; e < 8; e++)
                dst[lane + 32 * e] = src[lane + 32 * e];
        }
    }
}

__global__ void finalize_k(float* out, long long sidx, long long out_size) {
    if (threadIdx.x == 0 && blockIdx.x == 0) {
        float tc = 0.f;
        int nu = 0;
        for (int i = 0; i < BDIM * MAXSPAN; i++) tc += g_commit_span[i];
        for (int i = 0; i < BDIM; i++) nu += g_nact[i];
        if (sidx < out_size)
            out[sidx] = tc / (float)(nu > 0 ? nu : 1);
    }
}

extern "C" void kernel_launch(void* const* d_in, const int* in_sizes, int n_in,
                              void* d_out, int out_size) {
    const float* h    = (const float*)d_in[0];
    const int*   bidx = (const int*)d_in[1];
    const int*   spos = (const int*)d_in[2];
    const int*   tok  = (const int*)d_in[3];
    const int*   ctag = nullptr;
    int o = 4;
    if (n_in >= 11) { ctag = (const int*)d_in[4]; o = 5; }
    const float* W_ih  = (const float*)d_in[o + 0];
    const float* W_hh  = (const float*)d_in[o + 1];
    const float* b_ih  = (const float*)d_in[o + 2];
    const float* b_hh  = (const float*)d_in[o + 3];
    const float* cb    = (const float*)d_in[o + 4];
    const float* W_inj = (const float*)d_in[o + 5];
    float* out = (float*)d_out;

    static int smem_set = 0;
    if (!smem_set) {
        cudaFuncSetAttribute(span_scan,
                             cudaFuncAttributeMaxDynamicSharedMemorySize,
                             KCB * 512 * (int)sizeof(__nv_bfloat162));
        smem_set = 1;
    }

    cudaMemsetAsync(out, 0, (size_t)out_size * sizeof(float), 0);
    gather_x<<<NTAGS, 256>>>(h, bidx, spos);
    prep_cb<<<KCB + 1, 256>>>(cb);
    build_sched<<<BDIM, 512>>>(bidx, spos, tok, ctag);
    gru_concat<<<BDIM, 512>>>();
    fused_gemm<<<880, 128>>>(h, bidx, spos, W_ih, b_ih, W_hh, b_hh, W_inj);
    span_scan<<<BDIM * MAXSPAN, 1024, KCB * 512 * (int)sizeof(__nv_bfloat162)>>>();
    flush_k<<<BDIM, 1024>>>(out);
    finalize_k<<<1, 32>>>(out, (long long)BDIM * TDIM * DDIM, (long long)out_size);
}

// round 16
// speedup vs baseline: 1.0233x; 1.0233x over previous
#include <cuda_runtime.h>
#include <cuda_bf16.h>
#include <math.h>

// Problem constants
#define BDIM   8
#define TDIM   2048
#define DDIM   1024
#define EDIM   4
#define KCB    64
#define NTAGS  512
#define G3D    3072   // 3*DDIM
#define MAXSPAN 128

#define SCREEN_MARGIN 4.0f

// -------- scratch (device globals; no allocation allowed) --------
__device__ float g_X   [NTAGS * DDIM];
__device__ float g_Gih [NTAGS * G3D];         // compact GRU rows
__device__ float g_Ghh [(KCB + 1) * G3D];
__device__ float g_cb  [(KCB + 1) * DDIM];
__device__ __nv_bfloat162 g_cbH[KCB * 512];
__device__ float g_injT[KCB * DDIM];
__device__ float g_cnorm[KCB];
// schedule / span state
__device__ short g_st  [BDIM][NTAGS];
__device__ short g_sp2 [BDIM][NTAGS];
__device__ int   g_nact [BDIM];
__device__ int   g_nspan[BDIM];
__device__ short g_span_start[BDIM][MAXSPAN];
__device__ short g_span_len  [BDIM][MAXSPAN];
__device__ unsigned char g_code[BDIM][NTAGS];
__device__ float g_commit_span[BDIM * MAXSPAN];
// GRU-row compaction
__device__ short g_gruLocTag[BDIM][NTAGS];
__device__ short g_gihLoc[BDIM][NTAGS];
__device__ int   g_nGruB[BDIM];
__device__ int   g_gruOff[BDIM];
__device__ int   g_nGru;
__device__ short g_gruTag[NTAGS];

// ---- packed fp32x2 helpers ----
#define FFMA2(acc, a, bsp) \
    asm("fma.rn.f32x2 %0, %1, %2, %0;" : "+l"(acc) : "l"(a), "l"(bsp))
#define SPLAT2(d, f) \
    asm("mov.b64 %0, {%1, %1};" : "=l"(d) : "r"(__float_as_uint(f)))

// -------- gather h rows for each tag --------
__global__ void gather_x(const float* __restrict__ h,
                         const int* __restrict__ bidx,
                         const int* __restrict__ spos) {
    int t = blockIdx.x;
    int e = threadIdx.x;
    const float4* src = (const float4*)(h + ((size_t)bidx[t] * TDIM + spos[t]) * DDIM);
    float4* dst = (float4*)(g_X + (size_t)t * DDIM);
    dst[e] = src[e];
}

// -------- codebook copy (+zero row), norms, row-major bf16 copy --------
__global__ void prep_cb(const float* __restrict__ cb) {
    int k = blockIdx.x;
    int tid = threadIdx.x;
    float part = 0.f;
    for (int e = tid; e < DDIM; e += 256) {
        float v = (k < KCB) ? cb[(size_t)k * DDIM + e] : 0.f;
        g_cb[(size_t)k * DDIM + e] = v;
        part += v * v;
    }
    if (k < KCB) {
        for (int p = tid; p < 512; p += 256)
            g_cbH[k * 512 + p] = __floats2bfloat162_rn(cb[(size_t)k * DDIM + 2 * p],
                                                       cb[(size_t)k * DDIM + 2 * p + 1]);
    }
    __shared__ float red[256];
    red[tid] = part;
    __syncthreads();
    for (int s = 128; s > 0; s >>= 1) {
        if (tid < s) red[tid] += red[tid + s];
        __syncthreads();
    }
    if (tid == 0 && k < KCB) g_cnorm[k] = red[0];
}

// ============================================================================
// build_sched: per-batch active steps + span table + per-batch GRU compaction.
// ============================================================================
__global__ __launch_bounds__(512)
void build_sched(const int* __restrict__ bidx, const int* __restrict__ spos,
                 const int* __restrict__ tok, const int* __restrict__ ctag) {
    const int b = blockIdx.x;
    const int tid = threadIdx.x;
    __shared__ int s_scan[NTAGS];
    __shared__ int s_nchar, s_nact;

    const int char_tag = ctag ? *ctag : 0;
    const int inb  = (bidx[tid] == b) ? 1 : 0;
    const int isch = (inb && tok[tid] == char_tag) ? 1 : 0;
    s_scan[tid] = isch;
    __syncthreads();
    for (int off = 1; off < NTAGS; off <<= 1) {
        int v = s_scan[tid];
        if (tid >= off) v += s_scan[tid - off];
        __syncthreads();
        s_scan[tid] = v;
        __syncthreads();
    }
    const int chars_before = s_scan[tid] - isch;
    if (tid == NTAGS - 1) s_nchar = s_scan[NTAGS - 1];
    const int active = (inb && (isch || chars_before > 0)) ? 1 : 0;
    __syncthreads();
    s_scan[tid] = active;
    __syncthreads();
    for (int off = 1; off < NTAGS; off <<= 1) {
        int v = s_scan[tid];
        if (tid >= off) v += s_scan[tid - off];
        __syncthreads();
        s_scan[tid] = v;
        __syncthreads();
    }
    if (active) {
        int pos = s_scan[tid] - 1;
        g_st [b][pos] = (short)tid;
        g_sp2[b][pos] = (short)spos[tid];
        if (isch && chars_before < MAXSPAN)
            g_span_start[b][chars_before] = (short)pos;
        if (!isch) {
            int gl = pos - chars_before;
            g_gihLoc[b][pos] = (short)gl;
            g_gruLocTag[b][gl] = (short)tid;
        }
    }
    if (tid == NTAGS - 1) s_nact = s_scan[NTAGS - 1];
    __syncthreads();

    int nchar = s_nchar; if (nchar > MAXSPAN) nchar = MAXSPAN;
    const int nact = s_nact;
    for (int c = tid; c < MAXSPAN; c += 512) g_commit_span[b * MAXSPAN + c] = 0.f;
    if (tid < nchar) {
        int st = g_span_start[b][tid];
        int en = (tid + 1 < nchar) ? g_span_start[b][tid + 1] : nact;
        g_span_len[b][tid] = (short)(en - st);
    }
    if (tid == 0) {
        g_nspan[b] = nchar;
        g_nact[b] = nact;
        g_nGruB[b] = nact - s_nchar;
    }
}

// ---- concat per-batch GRU tag lists into global compact list ----
__global__ __launch_bounds__(512)
void gru_concat() {
    const int b = blockIdx.x;
    const int tid = threadIdx.x;
    int off = 0;
    for (int i = 0; i < b; i++) off += g_nGruB[i];
    const int n = g_nGruB[b];
    for (int i = tid; i < n; i += 512)
        g_gruTag[off + i] = g_gruLocTag[b][i];
    if (tid == 0) {
        g_gruOff[b] = off;
        if (b == 0) {
            int tot = 0;
            for (int i = 0; i < BDIM; i++) tot += g_nGruB[i];
            g_nGru = tot;
        }
    }
}

// ============================================================================
// Fused fp32 GEMM (single-K, proven tile): 64x64, BK=16, 128 threads, f32x2.
//   blocks [0,384):   Gih over COMPACT GRU rows (M=g_nGru); bm>=M -> exit
//   blocks [384,480): Ghh
//   blocks [480,496): injT
// ============================================================================
__global__ __launch_bounds__(128)
void fused_gemm(const float* __restrict__ h,
                const int* __restrict__ bidx, const int* __restrict__ spos,
                const float* __restrict__ W_ih, const float* __restrict__ b_ih,
                const float* __restrict__ W_hh, const float* __restrict__ b_hh,
                const float* __restrict__ W_inj)
{
    __shared__ __align__(16) float As[2][16][68];
    __shared__ __align__(16) float Bs[2][16][68];

    const int b = blockIdx.x;
    const float* Bw;
    const float* bias;
    float* C;
    const float* Abase = nullptr;
    int M, N, bm, bn, mode;
    if (b < 384) {
        mode = 0; N = G3D;
        bm = (b / 48) * 64; bn = (b % 48) * 64;
        M = g_nGru;
        if (bm >= M) return;                   // uniform exit before any barrier
        Bw = W_ih; bias = b_ih; C = g_Gih;
    } else if (b < 480) {
        int t = b - 384;
        mode = 1; M = KCB + 1; N = G3D;
        bm = (t / 48) * 64; bn = (t % 48) * 64;
        Bw = W_hh; bias = b_hh; C = g_Ghh; Abase = g_cb;
    } else {
        int t = b - 480;
        mode = 2; M = KCB; N = DDIM;
        bm = 0; bn = t * 64;
        Bw = W_inj; bias = nullptr; C = g_injT; Abase = g_cb;
    }

    const int tid   = threadIdx.x;
    const int r     = tid >> 1;
    const int halfq = (tid & 1) * 8;

    const float* aRow;
    {
        int gm = bm + r; if (gm > M - 1) gm = M - 1;
        if (mode == 0) {
            int tg = g_gruTag[gm];
            aRow = h + ((size_t)bidx[tg] * TDIM + spos[tg]) * DDIM;
        } else {
            aRow = Abase + (size_t)gm * DDIM;
        }
    }
    const float* bRow = Bw + (size_t)(bn + r) * DDIM;

    const int ty = tid >> 4;
    const int tx = tid & 15;

    unsigned long long acc[4][4];
#pragma unroll
    for (int p = 0; p < 4; p++)
#pragma unroll
        for (int j = 0; j < 4; j++) acc[p][j] = 0ull;

    {
        float4 a0 = *(const float4*)(aRow + halfq);
        float4 a1 = *(const float4*)(aRow + halfq + 4);
        float4 v0 = *(const float4*)(bRow + halfq);
        float4 v1 = *(const float4*)(bRow + halfq + 4);
        As[0][halfq + 0][r] = a0.x; As[0][halfq + 1][r] = a0.y;
        As[0][halfq + 2][r] = a0.z; As[0][halfq + 3][r] = a0.w;
        As[0][halfq + 4][r] = a1.x; As[0][halfq + 5][r] = a1.y;
        As[0][halfq + 6][r] = a1.z; As[0][halfq + 7][r] = a1.w;
        Bs[0][halfq + 0][r] = v0.x; Bs[0][halfq + 1][r] = v0.y;
        Bs[0][halfq + 2][r] = v0.z; Bs[0][halfq + 3][r] = v0.w;
        Bs[0][halfq + 4][r] = v1.x; Bs[0][halfq + 5][r] = v1.y;
        Bs[0][halfq + 6][r] = v1.z; Bs[0][halfq + 7][r] = v1.w;
    }
    __syncthreads();

    int buf = 0;
#pragma unroll 1
    for (int k0 = 0; k0 < DDIM; k0 += 16) {
        float4 na0, na1, nb0, nb1;
        const bool more = (k0 + 16) < DDIM;
        if (more) {
            const float* ap = aRow + k0 + 16 + halfq;
            na0 = *(const float4*)(ap);
            na1 = *(const float4*)(ap + 4);
            const float* bp = bRow + k0 + 16 + halfq;
            nb0 = *(const float4*)(bp);
            nb1 = *(const float4*)(bp + 4);
        }

#pragma unroll
        for (int kk = 0; kk < 16; kk++) {
            ulonglong2 aA = *(const ulonglong2*)&As[buf][kk][ty * 8];
            ulonglong2 aB = *(const ulonglong2*)&As[buf][kk][ty * 8 + 4];
            float4 bv = *(const float4*)&Bs[buf][kk][tx * 4];
            unsigned long long s0, s1, s2, s3;
            SPLAT2(s0, bv.x); SPLAT2(s1, bv.y);
            SPLAT2(s2, bv.z); SPLAT2(s3, bv.w);
            FFMA2(acc[0][0], aA.x, s0); FFMA2(acc[0][1], aA.x, s1);
            FFMA2(acc[0][2], aA.x, s2); FFMA2(acc[0][3], aA.x, s3);
            FFMA2(acc[1][0], aA.y, s0); FFMA2(acc[1][1], aA.y, s1);
            FFMA2(acc[1][2], aA.y, s2); FFMA2(acc[1][3], aA.y, s3);
            FFMA2(acc[2][0], aB.x, s0); FFMA2(acc[2][1], aB.x, s1);
            FFMA2(acc[2][2], aB.x, s2); FFMA2(acc[2][3], aB.x, s3);
            FFMA2(acc[3][0], aB.y, s0); FFMA2(acc[3][1], aB.y, s1);
            FFMA2(acc[3][2], aB.y, s2); FFMA2(acc[3][3], aB.y, s3);
        }

        if (more) {
            int nb = buf ^ 1;
            As[nb][halfq + 0][r] = na0.x; As[nb][halfq + 1][r] = na0.y;
            As[nb][halfq + 2][r] = na0.z; As[nb][halfq + 3][r] = na0.w;
            As[nb][halfq + 4][r] = na1.x; As[nb][halfq + 5][r] = na1.y;
            As[nb][halfq + 6][r] = na1.z; As[nb][halfq + 7][r] = na1.w;
            Bs[nb][halfq + 0][r] = nb0.x; Bs[nb][halfq + 1][r] = nb0.y;
            Bs[nb][halfq + 2][r] = nb0.z; Bs[nb][halfq + 3][r] = nb0.w;
            Bs[nb][halfq + 4][r] = nb1.x; Bs[nb][halfq + 5][r] = nb1.y;
            Bs[nb][halfq + 6][r] = nb1.z; Bs[nb][halfq + 7][r] = nb1.w;
        }
        __syncthreads();
        buf ^= 1;
    }

#pragma unroll
    for (int p = 0; p < 4; p++) {
        int gm0 = bm + ty * 8 + 2 * p;
#pragma unroll
        for (int j = 0; j < 4; j++) {
            int gn = bn + tx * 4 + j;
            float add = bias ? bias[gn] : 0.f;
            unsigned long long a = acc[p][j];
            float lo = __uint_as_float((unsigned)(a & 0xffffffffull)) + add;
            float hi = __uint_as_float((unsigned)(a >> 32)) + add;
            if (gm0 < M)     C[(size_t)gm0 * N + gn]       = lo;
            if (gm0 + 1 < M) C[(size_t)(gm0 + 1) * N + gn] = hi;
        }
    }
}

// ---- fast gates (MUFU) ----
__device__ __forceinline__ float fast_sigmoid(float x) {
    float e = __expf(-x);
    return __fdividef(1.f, 1.f + e);
}
__device__ __forceinline__ float fast_tanh(float x) {
    float e = __expf(-2.f * x);
    return __fdividef(1.f - e, 1.f + e);
}

// ============================================================================
// span_scan: one CTA per span; Gih read via compact index.
// ============================================================================
__global__ __launch_bounds__(1024)
void span_scan() {
    const int b = blockIdx.x / MAXSPAN;
    const int k = blockIdx.x % MAXSPAN;
    if (k >= g_nspan[b]) return;

    extern __shared__ __align__(16) __nv_bfloat162 s_cbh[];
    const int tid = threadIdx.x;
    const int lane = tid & 31;
    const int w = tid >> 5;

    __shared__ __align__(16) float zbuf[DDIM];
    __shared__ __align__(16) __nv_bfloat162 zbh[DDIM / 2];
    __shared__ float s_sd[64];
    __shared__ float s_cn[64];
    __shared__ float s_d[64];

    if (tid < 64) s_cn[tid] = g_cnorm[tid];
    for (int idx = tid; idx < KCB * 512; idx += 1024)
        s_cbh[idx] = g_cbH[idx];
    __syncthreads();

    const int start = g_span_start[b][k];
    const int len   = g_span_len[b][k];
    const int goff  = g_gruOff[b];

    float commit_acc = 0.f;
    int cur = 0;
    int spec_k = -1;
    float pf_gi0 = 0.f, pf_gi1 = 0.f, pf_gi2 = 0.f, pf_x = 0.f;
    float pf_gh0 = 0.f, pf_gh1 = 0.f, pf_gh2 = 0.f, pf_cur = 0.f;
    {
        int t0 = g_st[b][start];
        pf_x = g_X[(size_t)t0 * DDIM + tid];
    }

    for (int j = 0; j < len; j++) {
        // ---- phase A: z ----
        float zv;
        if (j == 0) {
            zv = pf_x;
        } else {
            float gh0, gh1, gh2, curv;
            if (cur == spec_k) {
                gh0 = pf_gh0; gh1 = pf_gh1; gh2 = pf_gh2; curv = pf_cur;
            } else {
                const float* gh = g_Ghh + (size_t)cur * G3D;
                gh0 = gh[tid]; gh1 = gh[1024 + tid]; gh2 = gh[2048 + tid];
                curv = g_cb[(size_t)cur * DDIM + tid];
            }
            float rr = fast_sigmoid(pf_gi0 + gh0);
            float zg = fast_sigmoid(pf_gi1 + gh1);
            float nn = fast_tanh(pf_gi2 + rr * gh2);
            zv = (1.f - zg) * nn + zg * curv;
        }
        zbuf[tid] = zv;
        {
            float partner = __shfl_xor_sync(0xffffffffu, zv, 1);
            if ((tid & 1) == 0)
                zbh[tid >> 1] = __floats2bfloat162_rn(zv, partner);
        }
        if (j + 1 < len) {
            int gidx = goff + (int)g_gihLoc[b][start + j + 1];
            const float* gi = g_Gih + (size_t)gidx * G3D;
            pf_gi0 = gi[tid]; pf_gi1 = gi[1024 + tid]; pf_gi2 = gi[2048 + tid];
        }
        __syncthreads();                       // sync 1

        // ---- phase B: HFMA2 screen; warp w -> codes 2w, 2w+1 ----
        {
            const int k0 = 2 * w;
            const uint4* zz4 = (const uint4*)zbh;
            const uint4* c0q = (const uint4*)(s_cbh + (size_t)k0 * 512);
            const uint4* c1q = c0q + 128;
            __nv_bfloat162 a00 = __floats2bfloat162_rn(0.f, 0.f);
            __nv_bfloat162 a01 = a00, a10 = a00, a11 = a00;
#pragma unroll
            for (int jq = 0; jq < 4; jq++) {
                uint4 zq = zz4[lane + 32 * jq];
                uint4 cA = c0q[lane + 32 * jq];
                uint4 cB = c1q[lane + 32 * jq];
                const __nv_bfloat162* zp = (const __nv_bfloat162*)&zq;
                const __nv_bfloat162* ap = (const __nv_bfloat162*)&cA;
                const __nv_bfloat162* bp = (const __nv_bfloat162*)&cB;
                a00 = __hfma2(zp[0], ap[0], a00);
                a01 = __hfma2(zp[1], ap[1], a01);
                a00 = __hfma2(zp[2], ap[2], a00);
                a01 = __hfma2(zp[3], ap[3], a01);
                a10 = __hfma2(zp[0], bp[0], a10);
                a11 = __hfma2(zp[1], bp[1], a11);
                a10 = __hfma2(zp[2], bp[2], a10);
                a11 = __hfma2(zp[3], bp[3], a11);
            }
            float2 u0 = __bfloat1622float2(a00);
            float2 u1 = __bfloat1622float2(a01);
            float2 v0 = __bfloat1622float2(a10);
            float2 v1 = __bfloat1622float2(a11);
            float p0 = (u0.x + u0.y) + (u1.x + u1.y);
            float p1 = (v0.x + v0.y) + (v1.x + v1.y);
#pragma unroll
            for (int off = 16; off; off >>= 1) {
                p0 += __shfl_down_sync(0xffffffffu, p0, off);
                p1 += __shfl_down_sync(0xffffffffu, p1, off);
            }
            if (lane == 0) {
                s_sd[k0]     = s_cn[k0]     - 2.f * p0;
                s_sd[k0 + 1] = s_cn[k0 + 1] - 2.f * p1;
            }
        }
        __syncthreads();                       // sync 2

        // ---- phase C: screened argmin (all warps) ----
        float v0c = s_sd[lane];
        float v1c = s_sd[lane + 32];
        float dm = v0c; int im = lane;
        if (v1c < dm) { dm = v1c; im = lane + 32; }
#pragma unroll
        for (int off = 16; off; off >>= 1) {
            float od = __shfl_xor_sync(0xffffffffu, dm, off);
            int   oi = __shfl_xor_sync(0xffffffffu, im, off);
            if (od < dm || (od == dm && oi < im)) { dm = od; im = oi; }
        }
        const int jb = 2 * w;
        const float dj0 = s_sd[jb];
        const float dj1 = s_sd[jb + 1];

        // speculative prefetch of next state row
        {
            const float* gh = g_Ghh + (size_t)im * G3D;
            pf_gh0 = gh[tid]; pf_gh1 = gh[1024 + tid]; pf_gh2 = gh[2048 + tid];
            pf_cur = g_cb[(size_t)im * DDIM + tid];
            spec_k = im;
        }

        // ---- phase D: exact fp32 recheck ----
        {
            const float4* z4 = (const float4*)zbuf;
            const float thr = dm + SCREEN_MARGIN;
#pragma unroll
            for (int jj = 0; jj < 2; jj++) {
                const int jc = jb + jj;
                const float dj = jj ? dj1 : dj0;
                float dx = INFINITY;
                if (dj <= thr) {
                    const float4* cr = (const float4*)(g_cb + (size_t)jc * DDIM);
                    float acc = 0.f;
#pragma unroll
                    for (int q = 0; q < 8; q++) {
                        float4 c = cr[lane + 32 * q];
                        float4 z = z4[lane + 32 * q];
                        float e0 = z.x - c.x, e1 = z.y - c.y;
                        float e2 = z.z - c.z, e3 = z.w - c.w;
                        acc += e0 * e0 + e1 * e1 + e2 * e2 + e3 * e3;
                    }
#pragma unroll
                    for (int off = 16; off; off >>= 1)
                        acc += __shfl_down_sync(0xffffffffu, acc, off);
                    dx = acc;
                }
                if (lane == 0) s_d[jc] = dx;
            }
        }
        __syncthreads();                       // sync 3

        // ---- phase E: exact argmin, state update ----
        {
            float e0 = s_d[lane];
            float e1 = s_d[lane + 32];
            float eb = e0; int ib = lane;
            if (e1 < eb) { eb = e1; ib = lane + 32; }
#pragma unroll
            for (int off = 16; off; off >>= 1) {
                float en = __shfl_xor_sync(0xffffffffu, eb, off);
                int   in_ = __shfl_xor_sync(0xffffffffu, ib, off);
                if (en < eb || (en == eb && in_ < ib)) { eb = en; ib = in_; }
            }
            cur = ib;
            if (tid == 0) {
                g_code[b][start + j] = (unsigned char)ib;
                commit_acc += eb * (1.f / 1024.f);
            }
            if (ib != im) spec_k = -1;
        }
    }

    if (tid == 0) g_commit_span[b * MAXSPAN + k] = commit_acc;
}

// ============================================================================
// flush: per-batch ordered injection writes (last-writer-wins per seq_pos).
// ============================================================================
__global__ __launch_bounds__(1024)
void flush_k(float* __restrict__ out) {
    const int b = blockIdx.x;
    const int tid = threadIdx.x;
    const int lane = tid & 31;
    const int w = tid >> 5;
    __shared__ short s_p2s[NTAGS];
    __shared__ unsigned char s_ck[NTAGS];
    const int nact = g_nact[b];
    for (int i = tid; i < nact; i += 1024) {
        s_p2s[i] = g_sp2[b][i];
        s_ck[i]  = g_code[b][i];
    }
    __syncthreads();
    for (int i = w; i < nact; i += 32) {
        const int p = s_p2s[i];
        bool dup = false;
        for (int j = i + 1 + lane; j < nact; j += 32)
            dup |= (s_p2s[j] == p);
        dup = __any_sync(0xffffffffu, dup);
        if (!dup) {
            const int k = s_ck[i];
            const float4* src = (const float4*)(g_injT + (size_t)k * DDIM);
            float4* dst = (float4*)(out + ((size_t)b * TDIM + p) * DDIM);
#pragma unroll
            for (int e = 0; e < 8; e++)
                dst[lane + 32 * e] = src[lane + 32 * e];
        }
    }
}

__global__ void finalize_k(float* out, long long sidx, long long out_size) {
    if (threadIdx.x == 0 && blockIdx.x == 0) {
        float tc = 0.f;
        int nu = 0;
        for (int i = 0; i < BDIM * MAXSPAN; i++) tc += g_commit_span[i];
        for (int i = 0; i < BDIM; i++) nu += g_nact[i];
        if (sidx < out_size)
            out[sidx] = tc / (float)(nu > 0 ? nu : 1);
    }
}

extern "C" void kernel_launch(void* const* d_in, const int* in_sizes, int n_in,
                              void* d_out, int out_size) {
    const float* h    = (const float*)d_in[0];
    const int*   bidx = (const int*)d_in[1];
    const int*   spos = (const int*)d_in[2];
    const int*   tok  = (const int*)d_in[3];
    const int*   ctag = nullptr;
    int o = 4;
    if (n_in >= 11) { ctag = (const int*)d_in[4]; o = 5; }
    const float* W_ih  = (const float*)d_in[o + 0];
    const float* W_hh  = (const float*)d_in[o + 1];
    const float* b_ih  = (const float*)d_in[o + 2];
    const float* b_hh  = (const float*)d_in[o + 3];
    const float* cb    = (const float*)d_in[o + 4];
    const float* W_inj = (const float*)d_in[o + 5];
    float* out = (float*)d_out;

    static int smem_set = 0;
    if (!smem_set) {
        cudaFuncSetAttribute(span_scan,
                             cudaFuncAttributeMaxDynamicSharedMemorySize,
                             KCB * 512 * (int)sizeof(__nv_bfloat162));
        smem_set = 1;
    }

    cudaMemsetAsync(out, 0, (size_t)out_size * sizeof(float), 0);
    gather_x<<<NTAGS, 256>>>(h, bidx, spos);
    prep_cb<<<KCB + 1, 256>>>(cb);
    build_sched<<<BDIM, 512>>>(bidx, spos, tok, ctag);
    gru_concat<<<BDIM, 512>>>();
    fused_gemm<<<496, 128>>>(h, bidx, spos, W_ih, b_ih, W_hh, b_hh, W_inj);
    span_scan<<<BDIM * MAXSPAN, 1024, KCB * 512 * (int)sizeof(__nv_bfloat162)>>>();
    flush_k<<<BDIM, 1024>>>(out);
    finalize_k<<<1, 32>>>(out, (long long)BDIM * TDIM * DDIM, (long long)out_size);
}

// round 17
// speedup vs baseline: 1.0987x; 1.0738x over previous
#include <cuda_runtime.h>
#include <cuda_bf16.h>
#include <math.h>

// Problem constants
#define BDIM   8
#define TDIM   2048
#define DDIM   1024
#define EDIM   4
#define KCB    64
#define NTAGS  512
#define G3D    3072   // 3*DDIM
#define MAXSPAN 128

#define SCREEN_MARGIN 4.0f

// prework grid layout
#define ZCTA   1024                       // zeroing CTAs (512thr x 8 float4 = 32KB... see code)
#define GCTA   (ZCTA + NTAGS)             // gather range end
#define PCTA   (GCTA + KCB + 1)           // prep_cb range end
#define BCTA   (PCTA + BDIM)              // build_sched range end

// -------- scratch (device globals; no allocation allowed) --------
__device__ float g_X   [NTAGS * DDIM];
__device__ float g_Gih [NTAGS * G3D];         // indexed by tag
__device__ float g_Ghh [(KCB + 1) * G3D];
__device__ float g_cb  [(KCB + 1) * DDIM];
__device__ __nv_bfloat162 g_cbH[KCB * 512];
__device__ float g_injT[KCB * DDIM];
__device__ float g_cnorm[KCB];
// schedule / span state
__device__ short g_st  [BDIM][NTAGS];
__device__ short g_sp2 [BDIM][NTAGS];
__device__ int   g_nact [BDIM];
__device__ int   g_nspan[BDIM];
__device__ short g_span_start[BDIM][MAXSPAN];
__device__ short g_span_len  [BDIM][MAXSPAN];
__device__ unsigned char g_code[BDIM][NTAGS];
__device__ float g_commit_span[BDIM * MAXSPAN];

// ---- packed fp32x2 helpers ----
#define FFMA2(acc, a, bsp) \
    asm("fma.rn.f32x2 %0, %1, %2, %0;" : "+l"(acc) : "l"(a), "l"(bsp))
#define SPLAT2(d, f) \
    asm("mov.b64 %0, {%1, %1};" : "=l"(d) : "r"(__float_as_uint(f)))

// ============================================================================
// prework: one launch, four independent jobs by CTA range (512 threads each):
//   [0,ZCTA):       zero the output tensor
//   [ZCTA,GCTA):    gather h rows per tag -> g_X
//   [GCTA,PCTA):    codebook copy (+zero row), norms, bf16 copy
//   [PCTA,BCTA):    per-batch schedule + span table
// ============================================================================
__global__ __launch_bounds__(512)
void prework(float* __restrict__ out, long long out_size,
             const float* __restrict__ h,
             const int* __restrict__ bidx, const int* __restrict__ spos,
             const int* __restrict__ tok, const int* __restrict__ ctag,
             const float* __restrict__ cb) {
    const int blk = blockIdx.x;
    const int tid = threadIdx.x;

    if (blk < ZCTA) {
        // ---- zero out: each CTA covers 4096 float4 (64KB) ----
        const long long n4 = out_size >> 2;
        long long base = (long long)blk * 4096 + tid;
        float4 z4 = make_float4(0.f, 0.f, 0.f, 0.f);
        float4* o4 = (float4*)out;
#pragma unroll
        for (int i = 0; i < 8; i++) {
            long long idx = base + (long long)i * 512;
            if (idx < n4) o4[idx] = z4;
        }
        if (blk == 0 && tid == 0)
            for (long long i = (n4 << 2); i < out_size; i++) out[i] = 0.f;
        return;
    }
    if (blk < GCTA) {
        // ---- gather one tag row ----
        int t = blk - ZCTA;
        if (tid < 256) {
            const float4* src = (const float4*)(h + ((size_t)bidx[t] * TDIM + spos[t]) * DDIM);
            float4* dst = (float4*)(g_X + (size_t)t * DDIM);
            dst[tid] = src[tid];
        }
        return;
    }
    if (blk < PCTA) {
        // ---- codebook prep (k in 0..64) ----
        int k = blk - GCTA;
        float part = 0.f;
        for (int e = tid; e < DDIM; e += 512) {
            float v = (k < KCB) ? cb[(size_t)k * DDIM + e] : 0.f;
            g_cb[(size_t)k * DDIM + e] = v;
            part += v * v;
        }
        if (k < KCB) {
            for (int p = tid; p < 512; p += 512)
                g_cbH[k * 512 + p] = __floats2bfloat162_rn(cb[(size_t)k * DDIM + 2 * p],
                                                           cb[(size_t)k * DDIM + 2 * p + 1]);
        }
        __shared__ float red[512];
        red[tid] = part;
        __syncthreads();
        for (int s = 256; s > 0; s >>= 1) {
            if (tid < s) red[tid] += red[tid + s];
            __syncthreads();
        }
        if (tid == 0 && k < KCB) g_cnorm[k] = red[0];
        return;
    }
    {
        // ---- build_sched for batch b ----
        const int b = blk - PCTA;
        __shared__ int s_scan[NTAGS];
        __shared__ int s_nchar, s_nact;

        const int char_tag = ctag ? *ctag : 0;
        const int inb  = (bidx[tid] == b) ? 1 : 0;
        const int isch = (inb && tok[tid] == char_tag) ? 1 : 0;
        s_scan[tid] = isch;
        __syncthreads();
        for (int off = 1; off < NTAGS; off <<= 1) {
            int v = s_scan[tid];
            if (tid >= off) v += s_scan[tid - off];
            __syncthreads();
            s_scan[tid] = v;
            __syncthreads();
        }
        const int chars_before = s_scan[tid] - isch;
        if (tid == NTAGS - 1) s_nchar = s_scan[NTAGS - 1];
        const int active = (inb && (isch || chars_before > 0)) ? 1 : 0;
        __syncthreads();
        s_scan[tid] = active;
        __syncthreads();
        for (int off = 1; off < NTAGS; off <<= 1) {
            int v = s_scan[tid];
            if (tid >= off) v += s_scan[tid - off];
            __syncthreads();
            s_scan[tid] = v;
            __syncthreads();
        }
        if (active) {
            int pos = s_scan[tid] - 1;
            g_st [b][pos] = (short)tid;
            g_sp2[b][pos] = (short)spos[tid];
            if (isch && chars_before < MAXSPAN)
                g_span_start[b][chars_before] = (short)pos;
        }
        if (tid == NTAGS - 1) s_nact = s_scan[NTAGS - 1];
        __syncthreads();

        int nchar = s_nchar; if (nchar > MAXSPAN) nchar = MAXSPAN;
        const int nact = s_nact;
        for (int c = tid; c < MAXSPAN; c += 512) g_commit_span[b * MAXSPAN + c] = 0.f;
        if (tid < nchar) {
            int st = g_span_start[b][tid];
            int en = (tid + 1 < nchar) ? g_span_start[b][tid + 1] : nact;
            g_span_len[b][tid] = (short)(en - st);
        }
        if (tid == 0) {
            g_nspan[b] = nchar;
            g_nact[b] = nact;
        }
    }
}

// ============================================================================
// Fused fp32 GEMM (round-14 proven): tile 64x64, BK=16, 128 threads, f32x2.
//   blocks [0,384):   Gih  (all 512 tag rows, gather fused)
//   blocks [384,480): Ghh
//   blocks [480,496): injT
// ============================================================================
__global__ __launch_bounds__(128)
void fused_gemm(const float* __restrict__ h,
                const int* __restrict__ bidx, const int* __restrict__ spos,
                const float* __restrict__ W_ih, const float* __restrict__ b_ih,
                const float* __restrict__ W_hh, const float* __restrict__ b_hh,
                const float* __restrict__ W_inj)
{
    __shared__ __align__(16) float As[2][16][68];
    __shared__ __align__(16) float Bs[2][16][68];

    const int b = blockIdx.x;
    const float* Bw;
    const float* bias;
    float* C;
    const float* Abase = nullptr;
    int M, N, bm, bn, mode;
    if (b < 384) {
        mode = 0; M = NTAGS; N = G3D;
        bm = (b / 48) * 64; bn = (b % 48) * 64;
        Bw = W_ih; bias = b_ih; C = g_Gih;
    } else if (b < 480) {
        int t = b - 384;
        mode = 1; M = KCB + 1; N = G3D;
        bm = (t / 48) * 64; bn = (t % 48) * 64;
        Bw = W_hh; bias = b_hh; C = g_Ghh; Abase = g_cb;
    } else {
        int t = b - 480;
        mode = 2; M = KCB; N = DDIM;
        bm = 0; bn = t * 64;
        Bw = W_inj; bias = nullptr; C = g_injT; Abase = g_cb;
    }

    const int tid   = threadIdx.x;
    const int r     = tid >> 1;
    const int halfq = (tid & 1) * 8;

    const float* aRow;
    {
        int gm = bm + r; if (gm > M - 1) gm = M - 1;
        if (mode == 0)
            aRow = h + ((size_t)bidx[gm] * TDIM + spos[gm]) * DDIM;
        else
            aRow = Abase + (size_t)gm * DDIM;
    }
    const float* bRow = Bw + (size_t)(bn + r) * DDIM;

    const int ty = tid >> 4;
    const int tx = tid & 15;

    unsigned long long acc[4][4];
#pragma unroll
    for (int p = 0; p < 4; p++)
#pragma unroll
        for (int j = 0; j < 4; j++) acc[p][j] = 0ull;

    {
        float4 a0 = *(const float4*)(aRow + halfq);
        float4 a1 = *(const float4*)(aRow + halfq + 4);
        float4 v0 = *(const float4*)(bRow + halfq);
        float4 v1 = *(const float4*)(bRow + halfq + 4);
        As[0][halfq + 0][r] = a0.x; As[0][halfq + 1][r] = a0.y;
        As[0][halfq + 2][r] = a0.z; As[0][halfq + 3][r] = a0.w;
        As[0][halfq + 4][r] = a1.x; As[0][halfq + 5][r] = a1.y;
        As[0][halfq + 6][r] = a1.z; As[0][halfq + 7][r] = a1.w;
        Bs[0][halfq + 0][r] = v0.x; Bs[0][halfq + 1][r] = v0.y;
        Bs[0][halfq + 2][r] = v0.z; Bs[0][halfq + 3][r] = v0.w;
        Bs[0][halfq + 4][r] = v1.x; Bs[0][halfq + 5][r] = v1.y;
        Bs[0][halfq + 6][r] = v1.z; Bs[0][halfq + 7][r] = v1.w;
    }
    __syncthreads();

    int buf = 0;
#pragma unroll 1
    for (int k0 = 0; k0 < DDIM; k0 += 16) {
        float4 na0, na1, nb0, nb1;
        const bool more = (k0 + 16) < DDIM;
        if (more) {
            const float* ap = aRow + k0 + 16 + halfq;
            na0 = *(const float4*)(ap);
            na1 = *(const float4*)(ap + 4);
            const float* bp = bRow + k0 + 16 + halfq;
            nb0 = *(const float4*)(bp);
            nb1 = *(const float4*)(bp + 4);
        }

#pragma unroll
        for (int kk = 0; kk < 16; kk++) {
            ulonglong2 aA = *(const ulonglong2*)&As[buf][kk][ty * 8];
            ulonglong2 aB = *(const ulonglong2*)&As[buf][kk][ty * 8 + 4];
            float4 bv = *(const float4*)&Bs[buf][kk][tx * 4];
            unsigned long long s0, s1, s2, s3;
            SPLAT2(s0, bv.x); SPLAT2(s1, bv.y);
            SPLAT2(s2, bv.z); SPLAT2(s3, bv.w);
            FFMA2(acc[0][0], aA.x, s0); FFMA2(acc[0][1], aA.x, s1);
            FFMA2(acc[0][2], aA.x, s2); FFMA2(acc[0][3], aA.x, s3);
            FFMA2(acc[1][0], aA.y, s0); FFMA2(acc[1][1], aA.y, s1);
            FFMA2(acc[1][2], aA.y, s2); FFMA2(acc[1][3], aA.y, s3);
            FFMA2(acc[2][0], aB.x, s0); FFMA2(acc[2][1], aB.x, s1);
            FFMA2(acc[2][2], aB.x, s2); FFMA2(acc[2][3], aB.x, s3);
            FFMA2(acc[3][0], aB.y, s0); FFMA2(acc[3][1], aB.y, s1);
            FFMA2(acc[3][2], aB.y, s2); FFMA2(acc[3][3], aB.y, s3);
        }

        if (more) {
            int nb = buf ^ 1;
            As[nb][halfq + 0][r] = na0.x; As[nb][halfq + 1][r] = na0.y;
            As[nb][halfq + 2][r] = na0.z; As[nb][halfq + 3][r] = na0.w;
            As[nb][halfq + 4][r] = na1.x; As[nb][halfq + 5][r] = na1.y;
            As[nb][halfq + 6][r] = na1.z; As[nb][halfq + 7][r] = na1.w;
            Bs[nb][halfq + 0][r] = nb0.x; Bs[nb][halfq + 1][r] = nb0.y;
            Bs[nb][halfq + 2][r] = nb0.z; Bs[nb][halfq + 3][r] = nb0.w;
            Bs[nb][halfq + 4][r] = nb1.x; Bs[nb][halfq + 5][r] = nb1.y;
            Bs[nb][halfq + 6][r] = nb1.z; Bs[nb][halfq + 7][r] = nb1.w;
        }
        __syncthreads();
        buf ^= 1;
    }

#pragma unroll
    for (int p = 0; p < 4; p++) {
        int gm0 = bm + ty * 8 + 2 * p;
#pragma unroll
        for (int j = 0; j < 4; j++) {
            int gn = bn + tx * 4 + j;
            float add = bias ? bias[gn] : 0.f;
            unsigned long long a = acc[p][j];
            float lo = __uint_as_float((unsigned)(a & 0xffffffffull)) + add;
            float hi = __uint_as_float((unsigned)(a >> 32)) + add;
            if (gm0 < M)     C[(size_t)gm0 * N + gn]       = lo;
            if (gm0 + 1 < M) C[(size_t)(gm0 + 1) * N + gn] = hi;
        }
    }
}

// ---- fast gates (MUFU) ----
__device__ __forceinline__ float fast_sigmoid(float x) {
    float e = __expf(-x);
    return __fdividef(1.f, 1.f + e);
}
__device__ __forceinline__ float fast_tanh(float x) {
    float e = __expf(-2.f * x);
    return __fdividef(1.f - e, 1.f + e);
}

// ============================================================================
// span_scan (round-14 proven): one CTA per span, Gih indexed by tag (g_st).
// uint4-vectorized codebook preload.
// ============================================================================
__global__ __launch_bounds__(1024)
void span_scan() {
    const int b = blockIdx.x / MAXSPAN;
    const int k = blockIdx.x % MAXSPAN;
    if (k >= g_nspan[b]) return;

    extern __shared__ __align__(16) __nv_bfloat162 s_cbh[];
    const int tid = threadIdx.x;
    const int lane = tid & 31;
    const int w = tid >> 5;

    __shared__ __align__(16) float zbuf[DDIM];
    __shared__ __align__(16) __nv_bfloat162 zbh[DDIM / 2];
    __shared__ float s_sd[64];
    __shared__ float s_cn[64];
    __shared__ float s_d[64];

    if (tid < 64) s_cn[tid] = g_cnorm[tid];
    {
        const uint4* src = (const uint4*)g_cbH;      // 128KB = 8192 uint4
        uint4* dst = (uint4*)s_cbh;
#pragma unroll
        for (int i = 0; i < 8; i++)
            dst[tid + 1024 * i] = src[tid + 1024 * i];
    }
    __syncthreads();

    const int start = g_span_start[b][k];
    const int len   = g_span_len[b][k];

    float commit_acc = 0.f;
    int cur = 0;
    int spec_k = -1;
    float pf_gi0 = 0.f, pf_gi1 = 0.f, pf_gi2 = 0.f, pf_x = 0.f;
    float pf_gh0 = 0.f, pf_gh1 = 0.f, pf_gh2 = 0.f, pf_cur = 0.f;
    {
        int t0 = g_st[b][start];
        pf_x = g_X[(size_t)t0 * DDIM + tid];         // step 0 is always the char
    }

    for (int j = 0; j < len; j++) {
        // ---- phase A: z ----
        float zv;
        if (j == 0) {
            zv = pf_x;
        } else {
            float gh0, gh1, gh2, curv;
            if (cur == spec_k) {
                gh0 = pf_gh0; gh1 = pf_gh1; gh2 = pf_gh2; curv = pf_cur;
            } else {
                const float* gh = g_Ghh + (size_t)cur * G3D;
                gh0 = gh[tid]; gh1 = gh[1024 + tid]; gh2 = gh[2048 + tid];
                curv = g_cb[(size_t)cur * DDIM + tid];
            }
            float rr = fast_sigmoid(pf_gi0 + gh0);
            float zg = fast_sigmoid(pf_gi1 + gh1);
            float nn = fast_tanh(pf_gi2 + rr * gh2);
            zv = (1.f - zg) * nn + zg * curv;
        }
        zbuf[tid] = zv;
        {
            float partner = __shfl_xor_sync(0xffffffffu, zv, 1);
            if ((tid & 1) == 0)
                zbh[tid >> 1] = __floats2bfloat162_rn(zv, partner);
        }
        if (j + 1 < len) {
            int t2 = g_st[b][start + j + 1];
            const float* gi = g_Gih + (size_t)t2 * G3D;
            pf_gi0 = gi[tid]; pf_gi1 = gi[1024 + tid]; pf_gi2 = gi[2048 + tid];
        }
        __syncthreads();                       // sync 1

        // ---- phase B: HFMA2 screen; warp w -> codes 2w, 2w+1 ----
        {
            const int k0 = 2 * w;
            const uint4* zz4 = (const uint4*)zbh;
            const uint4* c0q = (const uint4*)(s_cbh + (size_t)k0 * 512);
            const uint4* c1q = c0q + 128;
            __nv_bfloat162 a00 = __floats2bfloat162_rn(0.f, 0.f);
            __nv_bfloat162 a01 = a00, a10 = a00, a11 = a00;
#pragma unroll
            for (int jq = 0; jq < 4; jq++) {
                uint4 zq = zz4[lane + 32 * jq];
                uint4 cA = c0q[lane + 32 * jq];
                uint4 cB = c1q[lane + 32 * jq];
                const __nv_bfloat162* zp = (const __nv_bfloat162*)&zq;
                const __nv_bfloat162* ap = (const __nv_bfloat162*)&cA;
                const __nv_bfloat162* bp = (const __nv_bfloat162*)&cB;
                a00 = __hfma2(zp[0], ap[0], a00);
                a01 = __hfma2(zp[1], ap[1], a01);
                a00 = __hfma2(zp[2], ap[2], a00);
                a01 = __hfma2(zp[3], ap[3], a01);
                a10 = __hfma2(zp[0], bp[0], a10);
                a11 = __hfma2(zp[1], bp[1], a11);
                a10 = __hfma2(zp[2], bp[2], a10);
                a11 = __hfma2(zp[3], bp[3], a11);
            }
            float2 u0 = __bfloat1622float2(a00);
            float2 u1 = __bfloat1622float2(a01);
            float2 v0 = __bfloat1622float2(a10);
            float2 v1 = __bfloat1622float2(a11);
            float p0 = (u0.x + u0.y) + (u1.x + u1.y);
            float p1 = (v0.x + v0.y) + (v1.x + v1.y);
#pragma unroll
            for (int off = 16; off; off >>= 1) {
                p0 += __shfl_down_sync(0xffffffffu, p0, off);
                p1 += __shfl_down_sync(0xffffffffu, p1, off);
            }
            if (lane == 0) {
                s_sd[k0]     = s_cn[k0]     - 2.f * p0;
                s_sd[k0 + 1] = s_cn[k0 + 1] - 2.f * p1;
            }
        }
        __syncthreads();                       // sync 2

        // ---- phase C: screened argmin (all warps) ----
        float v0c = s_sd[lane];
        float v1c = s_sd[lane + 32];
        float dm = v0c; int im = lane;
        if (v1c < dm) { dm = v1c; im = lane + 32; }
#pragma unroll
        for (int off = 16; off; off >>= 1) {
            float od = __shfl_xor_sync(0xffffffffu, dm, off);
            int   oi = __shfl_xor_sync(0xffffffffu, im, off);
            if (od < dm || (od == dm && oi < im)) { dm = od; im = oi; }
        }
        const int jb = 2 * w;
        const float dj0 = s_sd[jb];
        const float dj1 = s_sd[jb + 1];

        // speculative prefetch of next state row
        {
            const float* gh = g_Ghh + (size_t)im * G3D;
            pf_gh0 = gh[tid]; pf_gh1 = gh[1024 + tid]; pf_gh2 = gh[2048 + tid];
            pf_cur = g_cb[(size_t)im * DDIM + tid];
            spec_k = im;
        }

        // ---- phase D: exact fp32 recheck ----
        {
            const float4* z4 = (const float4*)zbuf;
            const float thr = dm + SCREEN_MARGIN;
#pragma unroll
            for (int jj = 0; jj < 2; jj++) {
                const int jc = jb + jj;
                const float dj = jj ? dj1 : dj0;
                float dx = INFINITY;
                if (dj <= thr) {
                    const float4* cr = (const float4*)(g_cb + (size_t)jc * DDIM);
                    float acc = 0.f;
#pragma unroll
                    for (int q = 0; q < 8; q++) {
                        float4 c = cr[lane + 32 * q];
                        float4 z = z4[lane + 32 * q];
                        float e0 = z.x - c.x, e1 = z.y - c.y;
                        float e2 = z.z - c.z, e3 = z.w - c.w;
                        acc += e0 * e0 + e1 * e1 + e2 * e2 + e3 * e3;
                    }
#pragma unroll
                    for (int off = 16; off; off >>= 1)
                        acc += __shfl_down_sync(0xffffffffu, acc, off);
                    dx = acc;
                }
                if (lane == 0) s_d[jc] = dx;
            }
        }
        __syncthreads();                       // sync 3

        // ---- phase E: exact argmin, state update ----
        {
            float e0 = s_d[lane];
            float e1 = s_d[lane + 32];
            float eb = e0; int ib = lane;
            if (e1 < eb) { eb = e1; ib = lane + 32; }
#pragma unroll
            for (int off = 16; off; off >>= 1) {
                float en = __shfl_xor_sync(0xffffffffu, eb, off);
                int   in_ = __shfl_xor_sync(0xffffffffu, ib, off);
                if (en < eb || (en == eb && in_ < ib)) { eb = en; ib = in_; }
            }
            cur = ib;
            if (tid == 0) {
                g_code[b][start + j] = (unsigned char)ib;
                commit_acc += eb * (1.f / 1024.f);
            }
            if (ib != im) spec_k = -1;
        }
    }

    if (tid == 0) g_commit_span[b * MAXSPAN + k] = commit_acc;
}

// ============================================================================
// flush + finalize merged: blocks [0,BDIM) do ordered injection writes;
// block BDIM computes the avg-commit scalar (independent of the writes).
// ============================================================================
__global__ __launch_bounds__(1024)
void flush_fin(float* __restrict__ out, long long sidx, long long out_size) {
    const int b = blockIdx.x;
    const int tid = threadIdx.x;
    if (b == BDIM) {
        if (tid == 0) {
            float tc = 0.f;
            int nu = 0;
            for (int i = 0; i < BDIM * MAXSPAN; i++) tc += g_commit_span[i];
            for (int i = 0; i < BDIM; i++) nu += g_nact[i];
            if (sidx < out_size)
                out[sidx] = tc / (float)(nu > 0 ? nu : 1);
        }
        return;
    }
    const int lane = tid & 31;
    const int w = tid >> 5;
    __shared__ short s_p2s[NTAGS];
    __shared__ unsigned char s_ck[NTAGS];
    const int nact = g_nact[b];
    for (int i = tid; i < nact; i += 1024) {
        s_p2s[i] = g_sp2[b][i];
        s_ck[i]  = g_code[b][i];
    }
    __syncthreads();
    for (int i = w; i < nact; i += 32) {
        const int p = s_p2s[i];
        bool dup = false;
        for (int j = i + 1 + lane; j < nact; j += 32)
            dup |= (s_p2s[j] == p);
        dup = __any_sync(0xffffffffu, dup);
        if (!dup) {
            const int k = s_ck[i];
            const float4* src = (const float4*)(g_injT + (size_t)k * DDIM);
            float4* dst = (float4*)(out + ((size_t)b * TDIM + p) * DDIM);
#pragma unroll
            for (int e = 0; e < 8; e++)
                dst[lane + 32 * e] = src[lane + 32 * e];
        }
    }
}

extern "C" void kernel_launch(void* const* d_in, const int* in_sizes, int n_in,
                              void* d_out, int out_size) {
    const float* h    = (const float*)d_in[0];
    const int*   bidx = (const int*)d_in[1];
    const int*   spos = (const int*)d_in[2];
    const int*   tok  = (const int*)d_in[3];
    const int*   ctag = nullptr;
    int o = 4;
    if (n_in >= 11) { ctag = (const int*)d_in[4]; o = 5; }
    const float* W_ih  = (const float*)d_in[o + 0];
    const float* W_hh  = (const float*)d_in[o + 1];
    const float* b_ih  = (const float*)d_in[o + 2];
    const float* b_hh  = (const float*)d_in[o + 3];
    const float* cb    = (const float*)d_in[o + 4];
    const float* W_inj = (const float*)d_in[o + 5];
    float* out = (float*)d_out;

    static int smem_set = 0;
    if (!smem_set) {
        cudaFuncSetAttribute(span_scan,
                             cudaFuncAttributeMaxDynamicSharedMemorySize,
                             KCB * 512 * (int)sizeof(__nv_bfloat162));
        smem_set = 1;
    }

    prework<<<BCTA, 512>>>(out, (long long)out_size, h, bidx, spos, tok, ctag, cb);
    fused_gemm<<<496, 128>>>(h, bidx, spos, W_ih, b_ih, W_hh, b_hh, W_inj);
    span_scan<<<BDIM * MAXSPAN, 1024, KCB * 512 * (int)sizeof(__nv_bfloat162)>>>();
    flush_fin<<<BDIM + 1, 1024>>>(out, (long long)BDIM * TDIM * DDIM, (long long)out_size);
}